// round 1
// baseline (speedup 1.0000x reference)
#include <cuda_runtime.h>
#include <cuda_bf16.h>
#include <stdint.h>

#define NSLOTS 4096
#define TPB 512
#define PER_THREAD 8   // NSLOTS / TPB
#define KMAX 1024
#define EPSF 1e-3f

__global__ __launch_bounds__(TPB) void latent_handler_kernel(
    const float* __restrict__ z_where,
    const float* __restrict__ z_present,
    const float* __restrict__ z_what_loc,
    const float* __restrict__ z_depth_loc,
    const float* __restrict__ neg_priority,
    float* __restrict__ out,
    int B, int K)
{
    __shared__ unsigned int  s_keys[NSLOTS];
    __shared__ unsigned char s_flag[NSLOTS];   // 0 = absent/drop, 1 = present, 2 = negative
    __shared__ int s_hist[256];
    __shared__ int s_wsum[TPB / 32];
    __shared__ int s_scal[4];                  // 0: n_present, 1: prefix, 2: t_rem, 3: cnt_eq
    __shared__ int s_idxmap[KMAX];

    const int b    = blockIdx.x;
    const int tid  = threadIdx.x;
    const int lane = tid & 31;
    const int warp = tid >> 5;
    const int base = tid * PER_THREAD;

    if (tid < 4) s_scal[tid] = (tid == 3) ? -1 : 0;
    __syncthreads();

    // ---------------- Phase A: load presence + priority keys ----------------
    int my_present = 0;
    const float4* zp4 = (const float4*)(z_present    + (size_t)b * NSLOTS);
    const float4* np4 = (const float4*)(neg_priority + (size_t)b * NSLOTS);
    #pragma unroll
    for (int v = 0; v < 2; v++) {
        float4 p = zp4[tid * 2 + v];
        float4 q = np4[tid * 2 + v];
        float pv[4] = {p.x, p.y, p.z, p.w};
        float qv[4] = {q.x, q.y, q.z, q.w};
        #pragma unroll
        for (int j = 0; j < 4; j++) {
            int i = base + v * 4 + j;
            bool pres = pv[j] > EPSF;
            my_present += pres ? 1 : 0;
            s_flag[i] = pres ? 1 : 0;
            s_keys[i] = pres ? 0xFFFFFFFFu : __float_as_uint(qv[j]);
        }
    }
    #pragma unroll
    for (int o = 16; o; o >>= 1) my_present += __shfl_down_sync(0xFFFFFFFFu, my_present, o);
    if (lane == 0) atomicAdd(&s_scal[0], my_present);
    __syncthreads();

    const int n_present = s_scal[0];
    const int n_neg = K - n_present;
    if (tid == 0) { s_scal[1] = 0; s_scal[2] = n_neg; }
    __syncthreads();

    // ---------------- Phase B: radix select n_neg-th smallest key ----------------
    if (n_neg > 0) {
        #pragma unroll
        for (int pass = 0; pass < 4; pass++) {
            const int shift = 24 - 8 * pass;
            if (tid < 256) s_hist[tid] = 0;
            __syncthreads();
            const unsigned int pref = (unsigned int)s_scal[1];
            const int t_cur = s_scal[2];
            const int hishift = (shift + 8) & 31;
            #pragma unroll
            for (int j = 0; j < PER_THREAD; j++) {
                unsigned int key = s_keys[base + j];
                bool match = (pass == 0) || ((key >> hishift) == pref);
                if (match) atomicAdd(&s_hist[(key >> shift) & 0xFF], 1);
            }
            __syncthreads();
            // parallel find of the selected bin via scan over 256 bins
            int c = (tid < 256) ? s_hist[tid] : 0;
            int incl = c;
            #pragma unroll
            for (int o = 1; o < 32; o <<= 1) {
                int v = __shfl_up_sync(0xFFFFFFFFu, incl, o);
                if (lane >= o) incl += v;
            }
            if (tid < 256 && lane == 31) s_wsum[warp] = incl;
            __syncthreads();
            if (warp == 0 && lane < 8) {
                int v = s_wsum[lane];
                int vs = v;
                #pragma unroll
                for (int o = 1; o < 8; o <<= 1) {
                    int t2 = __shfl_up_sync(0xFFu, vs, o);
                    if (lane >= o) vs += t2;
                }
                s_wsum[lane] = vs - v;  // exclusive warp offsets
            }
            __syncthreads();
            if (tid < 256) {
                incl += s_wsum[warp];
                int excl = incl - c;
                if (incl >= t_cur && excl < t_cur) {   // unique winner
                    s_scal[1] = (int)((pref << 8) | (unsigned)tid);
                    s_scal[2] = t_cur - excl;
                    s_scal[3] = c;
                }
            }
            __syncthreads();
        }
    }

    const unsigned int Kstar = (unsigned int)s_scal[1];
    const int t_rem  = s_scal[2];
    const int cnt_eq = s_scal[3];

    // ---------------- Phase C: mark negatives ----------------
    #pragma unroll
    for (int j = 0; j < PER_THREAD; j++) {
        int i = base + j;
        if (s_flag[i] == 0 && n_neg > 0) {
            unsigned int key = s_keys[i];
            bool neg = false;
            if (key < Kstar) neg = true;
            else if (key == Kstar) {
                if (t_rem == cnt_eq) neg = true;
                else {
                    // tie-break by index (matches stable argsort) — ~never taken
                    int r = 0;
                    for (int q = 0; q < i; q++) r += (s_keys[q] == Kstar) ? 1 : 0;
                    neg = (r < t_rem);
                }
            }
            if (neg) s_flag[i] = 2;
        }
    }
    __syncthreads();

    // ---------------- Phase D: exclusive scan of keep flags -> idxmap ----------------
    int local[PER_THREAD];
    int sum = 0;
    #pragma unroll
    for (int j = 0; j < PER_THREAD; j++) {
        local[j] = sum;
        sum += (s_flag[base + j] != 0) ? 1 : 0;
    }
    int ws = sum;
    #pragma unroll
    for (int o = 1; o < 32; o <<= 1) {
        int v = __shfl_up_sync(0xFFFFFFFFu, ws, o);
        if (lane >= o) ws += v;
    }
    if (lane == 31) s_wsum[warp] = ws;
    __syncthreads();
    if (warp == 0 && lane < (TPB / 32)) {
        int v = s_wsum[lane];
        int vs = v;
        #pragma unroll
        for (int o = 1; o < (TPB / 32); o <<= 1) {
            int t2 = __shfl_up_sync(0xFFFFu, vs, o);
            if (lane >= o) vs += t2;
        }
        s_wsum[lane] = vs - v;  // exclusive
    }
    __syncthreads();
    const int thread_base = s_wsum[warp] + (ws - sum);
    #pragma unroll
    for (int j = 0; j < PER_THREAD; j++) {
        if (s_flag[base + j] != 0) {
            int p = thread_base + local[j];
            if (p < KMAX) s_idxmap[p] = base + j;
        }
    }
    __syncthreads();

    // ---------------- Phase E: gather + write outputs ----------------
    float* out_where = out;                               // [B, K, 4]
    float* out_mod   = out + (size_t)B * K * 4;           // [B, K, 1]
    float* out_what  = out + (size_t)B * K * 5;           // [B, K, 64]
    float* out_depth = out + (size_t)B * K * 69;          // [B, K, 1]

    const float4* zw4 = (const float4*)z_where + (size_t)b * NSLOTS;
    const float*  zd  = z_depth_loc + (size_t)b * NSLOTS;

    for (int p = tid; p < K; p += TPB) {
        int slot = s_idxmap[p];
        bool pres = (s_flag[slot] == 1);
        float4 w = zw4[slot];
        float m = fmaxf(w.z, w.w);
        ((float4*)out_where)[(size_t)b * K + p] = make_float4(w.x, w.y, m, m);
        out_mod[(size_t)b * K + p]   = pres ? 1.0f : -1.0f;
        out_depth[(size_t)b * K + p] = pres ? zd[slot] : 0.0f;
    }

    const float4* wl4 = (const float4*)z_what_loc + (size_t)b * NSLOTS * 16;
    float4* ow4 = (float4*)out_what + (size_t)b * K * 16;
    const int total = K * 16;
    for (int i = tid; i < total; i += TPB) {
        int p = i >> 4;
        int c = i & 15;
        int slot = s_idxmap[p];
        float4 v = make_float4(0.f, 0.f, 0.f, 0.f);
        if (s_flag[slot] == 1) v = wl4[slot * 16 + c];
        ow4[p * 16 + c] = v;
    }
}

extern "C" void kernel_launch(void* const* d_in, const int* in_sizes, int n_in,
                              void* d_out, int out_size) {
    const float* z_where      = (const float*)d_in[0];
    const float* z_present    = (const float*)d_in[1];
    const float* z_what_loc   = (const float*)d_in[2];
    // d_in[3] = z_what_scale  (never read: not in outputs)
    const float* z_depth_loc  = (const float*)d_in[4];
    // d_in[5] = z_depth_scale (never read)
    const float* neg_priority = (const float*)d_in[6];

    const int B = in_sizes[6] / NSLOTS;            // neg_priority is [B, N]
    const int K = out_size / (B * 70);             // 4 + 1 + 64 + 1 features

    latent_handler_kernel<<<B, TPB>>>(z_where, z_present, z_what_loc,
                                      z_depth_loc, neg_priority,
                                      (float*)d_out, B, K);
}

// round 2
// speedup vs baseline: 1.1763x; 1.1763x over previous
#include <cuda_runtime.h>
#include <stdint.h>

#define NSLOTS 4096
#define TPB 1024
#define PT 4            // NSLOTS / TPB
#define KMAX 1024
#define EPSF 1e-3f

// dynamic smem layout (bytes):
//   s_where  [4096] float4 : 65536
//   s_depth  [4096] float  : 16384
//   s_keys   [4096] uint   : 16384
//   s_flag   [4096] uchar  :  4096
//   s_idxmap [1024] int    :  4096
//   s_hist   [256]  int    :  1024
//   s_wsum   [32]   int    :   128
//   s_scal   [4]    int    :    16
#define SMEM_BYTES (65536 + 16384 + 16384 + 4096 + 4096 + 1024 + 128 + 16)

__device__ __forceinline__ void cp_async16(void* smem_dst, const void* gmem_src) {
    unsigned saddr = (unsigned)__cvta_generic_to_shared(smem_dst);
    asm volatile("cp.async.cg.shared.global [%0], [%1], 16;\n"
                 :: "r"(saddr), "l"(gmem_src) : "memory");
}

__global__ __launch_bounds__(TPB) void latent_handler_kernel(
    const float* __restrict__ z_where,
    const float* __restrict__ z_present,
    const float* __restrict__ z_what_loc,
    const float* __restrict__ z_depth_loc,
    const float* __restrict__ neg_priority,
    float* __restrict__ out,
    int B, int K)
{
    extern __shared__ char smem[];
    float4*        s_where  = (float4*)smem;
    float*         s_depth  = (float*)(smem + 65536);
    unsigned int*  s_keys   = (unsigned int*)(smem + 65536 + 16384);
    unsigned char* s_flag   = (unsigned char*)(smem + 65536 + 2 * 16384);
    int*           s_idxmap = (int*)(smem + 65536 + 2 * 16384 + 4096);
    int*           s_hist   = (int*)(smem + 65536 + 2 * 16384 + 2 * 4096);
    int*           s_wsum   = (int*)(smem + 65536 + 2 * 16384 + 2 * 4096 + 1024);
    int*           s_scal   = (int*)(smem + 65536 + 2 * 16384 + 2 * 4096 + 1024 + 128);

    const int b    = blockIdx.x;
    const int tid  = threadIdx.x;
    const int lane = tid & 31;
    const int warp = tid >> 5;
    const int base = tid * PT;

    // ---- Phase 0: async prefetch of z_where row (64KB) + z_depth row (16KB) ----
    {
        const float4* zw4 = (const float4*)z_where + (size_t)b * NSLOTS;
        #pragma unroll
        for (int v = 0; v < 4; v++)
            cp_async16(&s_where[tid + v * TPB], &zw4[tid + v * TPB]);
        const float4* zd4 = (const float4*)(z_depth_loc + (size_t)b * NSLOTS);
        cp_async16(&((float4*)s_depth)[tid], &zd4[tid]);
        asm volatile("cp.async.commit_group;\n" ::: "memory");
    }

    if (tid < 4) s_scal[tid] = (tid == 3) ? -1 : 0;
    __syncthreads();

    // ---- Phase A: presence + priority keys ----
    int my_present = 0;
    {
        float4 p = ((const float4*)(z_present    + (size_t)b * NSLOTS))[tid];
        float4 q = ((const float4*)(neg_priority + (size_t)b * NSLOTS))[tid];
        float pv[4] = {p.x, p.y, p.z, p.w};
        float qv[4] = {q.x, q.y, q.z, q.w};
        #pragma unroll
        for (int j = 0; j < 4; j++) {
            int i = base + j;
            bool pres = pv[j] > EPSF;
            my_present += pres ? 1 : 0;
            s_flag[i] = pres ? 1 : 0;
            s_keys[i] = pres ? 0xFFFFFFFFu : __float_as_uint(qv[j]);
        }
    }
    #pragma unroll
    for (int o = 16; o; o >>= 1) my_present += __shfl_down_sync(0xFFFFFFFFu, my_present, o);
    if (lane == 0) atomicAdd(&s_scal[0], my_present);
    __syncthreads();

    const int n_present = s_scal[0];
    const int n_neg = K - n_present;
    if (tid == 0) { s_scal[1] = 0; s_scal[2] = n_neg; }
    __syncthreads();

    // ---- Phase B: 4-pass radix select (3 barriers / pass) ----
    #pragma unroll
    for (int pass = 0; pass < 4; pass++) {
        const int shift = 24 - 8 * pass;
        if (tid < 256) s_hist[tid] = 0;
        __syncthreads();
        const unsigned int pref = (unsigned int)s_scal[1];
        const int t_cur = s_scal[2];
        const int hishift = (shift + 8) & 31;
        #pragma unroll
        for (int j = 0; j < PT; j++) {
            unsigned int key = s_keys[base + j];
            bool match = (pass == 0) || ((key >> hishift) == pref);
            if (match) atomicAdd(&s_hist[(key >> shift) & 0xFF], 1);
        }
        __syncthreads();
        if (warp == 0) {
            // warp-synchronous 256-bin scan + winner find: lane owns bins [lane*8, lane*8+8)
            int c[8]; int tot = 0;
            #pragma unroll
            for (int j = 0; j < 8; j++) { c[j] = s_hist[lane * 8 + j]; tot += c[j]; }
            int sc = tot;
            #pragma unroll
            for (int o = 1; o < 32; o <<= 1) {
                int v = __shfl_up_sync(0xFFFFFFFFu, sc, o);
                if (lane >= o) sc += v;
            }
            int cum = sc - tot;  // exclusive base for this lane
            #pragma unroll
            for (int j = 0; j < 8; j++) {
                if (cum < t_cur && cum + c[j] >= t_cur) {
                    s_scal[1] = (int)((pref << 8) | (unsigned)(lane * 8 + j));
                    s_scal[2] = t_cur - cum;
                    s_scal[3] = c[j];
                }
                cum += c[j];
            }
        }
        __syncthreads();
    }

    const unsigned int Kstar = (unsigned int)s_scal[1];
    const int t_rem  = s_scal[2];
    const int cnt_eq = s_scal[3];

    // ---- Phase C+D fused: keep decision + exclusive scan -> idxmap ----
    int keep[PT], local[PT];
    int sum = 0;
    #pragma unroll
    for (int j = 0; j < PT; j++) {
        int i = base + j;
        bool kp = (s_flag[i] == 1);
        if (!kp && n_neg > 0) {
            unsigned int key = s_keys[i];
            if (key < Kstar) kp = true;
            else if (key == Kstar) {
                if (t_rem == cnt_eq) kp = true;
                else {
                    // stable tie-break by index (matches jnp.argsort); ~never taken
                    int r = 0;
                    for (int q = 0; q < i; q++) r += (s_keys[q] == Kstar) ? 1 : 0;
                    kp = (r < t_rem);
                }
            }
        }
        keep[j] = kp ? 1 : 0;
        local[j] = sum;
        sum += keep[j];
    }
    int ws = sum;
    #pragma unroll
    for (int o = 1; o < 32; o <<= 1) {
        int v = __shfl_up_sync(0xFFFFFFFFu, ws, o);
        if (lane >= o) ws += v;
    }
    if (lane == 31) s_wsum[warp] = ws;
    __syncthreads();
    if (warp == 0) {
        int v = s_wsum[lane];
        int vs = v;
        #pragma unroll
        for (int o = 1; o < 32; o <<= 1) {
            int t2 = __shfl_up_sync(0xFFFFFFFFu, vs, o);
            if (lane >= o) vs += t2;
        }
        s_wsum[lane] = vs - v;  // exclusive warp offsets
    }
    __syncthreads();
    const int thread_base = s_wsum[warp] + (ws - sum);
    #pragma unroll
    for (int j = 0; j < PT; j++) {
        if (keep[j]) {
            int p = thread_base + local[j];
            if (p < KMAX) s_idxmap[p] = base + j;
        }
    }
    asm volatile("cp.async.wait_group 0;\n" ::: "memory");
    __syncthreads();

    // ---- Phase E: gather + write outputs ----
    float* out_where = out;                               // [B, K, 4]
    float* out_mod   = out + (size_t)B * K * 4;           // [B, K, 1]
    float* out_what  = out + (size_t)B * K * 5;           // [B, K, 64]
    float* out_depth = out + (size_t)B * K * 69;          // [B, K, 1]

    for (int p = tid; p < K; p += TPB) {
        int slot = s_idxmap[p];
        bool pres = (s_flag[slot] == 1);
        float4 w = s_where[slot];
        float m = fmaxf(w.z, w.w);
        ((float4*)out_where)[(size_t)b * K + p] = make_float4(w.x, w.y, m, m);
        out_mod[(size_t)b * K + p]   = pres ? 1.0f : -1.0f;
        out_depth[(size_t)b * K + p] = pres ? s_depth[slot] : 0.0f;
    }

    const float4* wl4 = (const float4*)z_what_loc + (size_t)b * NSLOTS * 16;
    float4* ow4 = (float4*)out_what + (size_t)b * K * 16;
    const int total = K * 16;
    for (int i = tid; i < total; i += TPB) {
        int p = i >> 4;
        int c = i & 15;
        int slot = s_idxmap[p];
        float4 v = make_float4(0.f, 0.f, 0.f, 0.f);
        if (s_flag[slot] == 1) v = __ldg(&wl4[slot * 16 + c]);
        ow4[i] = v;
    }
}

extern "C" void kernel_launch(void* const* d_in, const int* in_sizes, int n_in,
                              void* d_out, int out_size) {
    const float* z_where      = (const float*)d_in[0];
    const float* z_present    = (const float*)d_in[1];
    const float* z_what_loc   = (const float*)d_in[2];
    // d_in[3] = z_what_scale  (never read: not in outputs)
    const float* z_depth_loc  = (const float*)d_in[4];
    // d_in[5] = z_depth_scale (never read)
    const float* neg_priority = (const float*)d_in[6];

    const int B = in_sizes[6] / NSLOTS;            // neg_priority is [B, N]
    const int K = out_size / (B * 70);             // 4 + 1 + 64 + 1 features

    cudaFuncSetAttribute(latent_handler_kernel,
                         cudaFuncAttributeMaxDynamicSharedMemorySize, SMEM_BYTES);

    latent_handler_kernel<<<B, TPB, SMEM_BYTES>>>(z_where, z_present, z_what_loc,
                                                  z_depth_loc, neg_priority,
                                                  (float*)d_out, B, K);
}

// round 3
// speedup vs baseline: 1.2917x; 1.0980x over previous
#include <cuda_runtime.h>
#include <stdint.h>

#define NSLOTS 4096
#define TPB 1024
#define PT 4            // NSLOTS / TPB
#define NBINS 4096
#define WHATROWS 256    // max prefetched present rows
#define EPSF 1e-3f

// dynamic smem layout (bytes)
#define OFF_WHERE   0                       // float4[4096]  65536
#define OFF_WHAT    65536                   // float4[256*16] 65536
#define OFF_DEPTH   131072                  // float[4096]   16384
#define OFF_KEYS    147456                  // uint[4096]    16384
#define OFF_HIST    163840                  // int[4096]     16384 (reused as candidate list)
#define OFF_DIG     180224                  // u16[4096]      8192
#define OFF_PRANK   188416                  // u16[4096]      8192
#define OFF_IDXMAP  196608                  // int[1024]      4096
#define OFF_PLIST   200704                  // int[256]       1024
#define OFF_WSUM    201728                  // int[32]         128
#define OFF_SCAL    201856                  // int[8]           32
#define SMEM_BYTES  201888

__device__ __forceinline__ void cp_async16(void* smem_dst, const void* gmem_src) {
    unsigned saddr = (unsigned)__cvta_generic_to_shared(smem_dst);
    asm volatile("cp.async.cg.shared.global [%0], [%1], 16;\n"
                 :: "r"(saddr), "l"(gmem_src) : "memory");
}

__global__ __launch_bounds__(TPB) void latent_handler_kernel(
    const float* __restrict__ z_where,
    const float* __restrict__ z_present,
    const float* __restrict__ z_what_loc,
    const float* __restrict__ z_depth_loc,
    const float* __restrict__ neg_priority,
    float* __restrict__ out,
    int B, int K)
{
    extern __shared__ char smem[];
    float4*         s_where  = (float4*)(smem + OFF_WHERE);
    float4*         s_what4  = (float4*)(smem + OFF_WHAT);
    float*          s_depth  = (float*) (smem + OFF_DEPTH);
    unsigned int*   s_keys   = (unsigned int*)(smem + OFF_KEYS);
    int*            s_hist   = (int*)   (smem + OFF_HIST);
    unsigned short* s_dig    = (unsigned short*)(smem + OFF_DIG);
    unsigned short* s_prank  = (unsigned short*)(smem + OFF_PRANK);
    int*            s_idxmap = (int*)   (smem + OFF_IDXMAP);
    int*            s_plist  = (int*)   (smem + OFF_PLIST);
    int*            s_wsum   = (int*)   (smem + OFF_WSUM);
    int*            s_scal   = (int*)   (smem + OFF_SCAL);

    const int b    = blockIdx.x;
    const int tid  = threadIdx.x;
    const int lane = tid & 31;
    const int warp = tid >> 5;
    const int base = tid * PT;

    // ---- prefetch z_where (64KB) + z_depth (16KB) for this row ----
    {
        const float4* zw4 = (const float4*)z_where + (size_t)b * NSLOTS;
        #pragma unroll
        for (int v = 0; v < 4; v++)
            cp_async16(&s_where[tid + v * TPB], &zw4[tid + v * TPB]);
        const float4* zd4 = (const float4*)(z_depth_loc + (size_t)b * NSLOTS);
        cp_async16(&((float4*)s_depth)[tid], &zd4[tid]);
    }

    // ---- load presence + priority, build keys/digits, present-rank scan ----
    int presf[PT], local[PT], digr[PT];
    int sum = 0;
    {
        float4 p = ((const float4*)(z_present    + (size_t)b * NSLOTS))[tid];
        float4 q = ((const float4*)(neg_priority + (size_t)b * NSLOTS))[tid];
        float pv[4] = {p.x, p.y, p.z, p.w};
        float qv[4] = {q.x, q.y, q.z, q.w};
        #pragma unroll
        for (int j = 0; j < PT; j++) {
            int i = base + j;
            bool pres = pv[j] > EPSF;
            presf[j] = pres ? 1 : 0;
            local[j] = sum;
            sum += presf[j];
            unsigned int bits = __float_as_uint(qv[j]);
            unsigned int msk  = (unsigned int)(((int)bits) >> 31) | 0x80000000u;
            s_keys[i] = pres ? 0xFFFFFFFFu : (bits ^ msk);   // order-preserving key
            int d = __float2int_rd(qv[j] * 4096.0f);          // exact ×2^12, monotone
            d = min(NBINS - 1, max(0, d));
            digr[j] = d;
            s_dig[i] = pres ? 0xFFFFu : (unsigned short)d;
        }
    }
    int ws = sum;
    #pragma unroll
    for (int o = 1; o < 32; o <<= 1) {
        int v = __shfl_up_sync(0xFFFFFFFFu, ws, o);
        if (lane >= o) ws += v;
    }
    if (lane == 31) s_wsum[warp] = ws;
    if (tid == 0) { s_scal[1] = -1; s_scal[4] = 0; }
    __syncthreads();                                          // B1
    if (warp == 0) {
        int v = s_wsum[lane];
        int vs = v;
        #pragma unroll
        for (int o = 1; o < 32; o <<= 1) {
            int t2 = __shfl_up_sync(0xFFFFFFFFu, vs, o);
            if (lane >= o) vs += t2;
        }
        s_wsum[lane] = vs - v;
        if (lane == 31) s_scal[0] = vs;                       // n_present total
    }
    __syncthreads();                                          // B2
    const int n_present = s_scal[0];
    const int n_neg = K - n_present;
    {
        int tb = s_wsum[warp] + (ws - sum);
        #pragma unroll
        for (int j = 0; j < PT; j++) {
            if (presf[j]) {
                int r = tb + local[j];
                s_prank[base + j] = (unsigned short)r;
                if (r < WHATROWS) s_plist[r] = base + j;
            }
        }
    }
    ((int4*)s_hist)[tid] = make_int4(0, 0, 0, 0);             // zero 4096-bin histogram
    __syncthreads();                                          // B3

    // ---- prefetch z_what rows for present slots (overlaps with selection) ----
    const float4* wl4 = (const float4*)z_what_loc + (size_t)b * NSLOTS * 16;
    {
        int npre = min(n_present, WHATROWS);
        for (int i = tid; i < npre * 16; i += TPB) {
            int slot = s_plist[i >> 4];
            cp_async16(&s_what4[i], &wl4[slot * 16 + (i & 15)]);
        }
        asm volatile("cp.async.commit_group;\n" ::: "memory");
    }

    // ---- single-pass value-bucket histogram (uniform bins -> low contention) ----
    #pragma unroll
    for (int j = 0; j < PT; j++)
        if (!presf[j]) atomicAdd(&s_hist[digr[j]], 1);
    __syncthreads();                                          // B4

    // ---- winner-bin search via block scan over 4096 bins ----
    {
        int4 cc = ((int4*)s_hist)[tid];
        int cb[4] = {cc.x, cc.y, cc.z, cc.w};
        int tot = cb[0] + cb[1] + cb[2] + cb[3];
        int sc = tot;
        #pragma unroll
        for (int o = 1; o < 32; o <<= 1) {
            int v = __shfl_up_sync(0xFFFFFFFFu, sc, o);
            if (lane >= o) sc += v;
        }
        if (lane == 31) s_wsum[warp] = sc;
        __syncthreads();                                      // B5
        if (warp == 0) {
            int v = s_wsum[lane];
            int vs = v;
            #pragma unroll
            for (int o = 1; o < 32; o <<= 1) {
                int t2 = __shfl_up_sync(0xFFFFFFFFu, vs, o);
                if (lane >= o) vs += t2;
            }
            s_wsum[lane] = vs - v;
        }
        __syncthreads();                                      // B6
        if (n_neg > 0) {
            int cum = s_wsum[warp] + (sc - tot);              // exclusive base
            #pragma unroll
            for (int j = 0; j < 4; j++) {
                if (cum < n_neg && n_neg <= cum + cb[j]) {
                    s_scal[1] = tid * 4 + j;                  // winner bin
                    s_scal[2] = n_neg - cum;                  // needed within bin
                    s_scal[3] = cb[j];                        // bin count
                }
                cum += cb[j];
            }
        }
    }
    __syncthreads();                                          // B7
    const int winbin = s_scal[1];
    const int t_rem  = s_scal[2];
    const int cnt_eq = s_scal[3];
    const bool need_exact = (winbin >= 0) && (t_rem < cnt_eq);

    // ---- exact stable tie-break inside winner bin (usually ~1-8 candidates) ----
    int* s_cand = s_hist;                                     // reuse histogram memory
    if (need_exact) {
        #pragma unroll
        for (int j = 0; j < PT; j++)
            if (!presf[j] && digr[j] == winbin)
                s_cand[atomicAdd(&s_scal[4], 1)] = base + j;
        __syncthreads();                                      // B8 (uniform branch)
    }

    // ---- keep decision + compaction scan -> idxmap ----
    int keep[PT];
    sum = 0;
    #pragma unroll
    for (int j = 0; j < PT; j++) {
        bool kp;
        if (presf[j]) kp = true;
        else if (winbin < 0) kp = false;
        else {
            int d = digr[j];
            if (d < winbin) kp = true;
            else if (d > winbin) kp = false;
            else if (!need_exact) kp = true;                  // whole bin selected
            else {
                unsigned int my = s_keys[base + j];
                int myi = base + j, r = 0, nc = s_scal[4];
                for (int t = 0; t < nc; t++) {
                    int ci = s_cand[t];
                    unsigned int ck = s_keys[ci];
                    r += (ck < my) || (ck == my && ci < myi);
                }
                kp = (r < t_rem);                             // stable (key, idx) rank
            }
        }
        keep[j] = kp ? 1 : 0;
        local[j] = sum;
        sum += keep[j];
    }
    ws = sum;
    #pragma unroll
    for (int o = 1; o < 32; o <<= 1) {
        int v = __shfl_up_sync(0xFFFFFFFFu, ws, o);
        if (lane >= o) ws += v;
    }
    if (lane == 31) s_wsum[warp] = ws;
    __syncthreads();                                          // B9
    if (warp == 0) {
        int v = s_wsum[lane];
        int vs = v;
        #pragma unroll
        for (int o = 1; o < 32; o <<= 1) {
            int t2 = __shfl_up_sync(0xFFFFFFFFu, vs, o);
            if (lane >= o) vs += t2;
        }
        s_wsum[lane] = vs - v;
    }
    __syncthreads();                                          // B10
    {
        int tb = s_wsum[warp] + (ws - sum);
        #pragma unroll
        for (int j = 0; j < PT; j++)
            if (keep[j]) {
                int p = tb + local[j];
                if (p < 1024) s_idxmap[p] = base + j;
            }
    }
    asm volatile("cp.async.wait_group 0;\n" ::: "memory");
    __syncthreads();                                          // B11

    // ---- epilogue: all sources in smem -> pure streaming stores ----
    float* out_where = out;                                   // [B, K, 4]
    float* out_mod   = out + (size_t)B * K * 4;               // [B, K, 1]
    float* out_what  = out + (size_t)B * K * 5;               // [B, K, 64]
    float* out_depth = out + (size_t)B * K * 69;              // [B, K, 1]

    for (int p = tid; p < K; p += TPB) {
        int slot = s_idxmap[p];
        bool pres = (s_dig[slot] == 0xFFFFu);
        float4 w = s_where[slot];
        float m = fmaxf(w.z, w.w);
        ((float4*)out_where)[(size_t)b * K + p] = make_float4(w.x, w.y, m, m);
        out_mod[(size_t)b * K + p]   = pres ? 1.0f : -1.0f;
        out_depth[(size_t)b * K + p] = pres ? s_depth[slot] : 0.0f;
    }

    float4* ow4 = (float4*)out_what + (size_t)b * K * 16;
    const int total = K * 16;
    for (int i = tid; i < total; i += TPB) {
        int p = i >> 4;
        int c = i & 15;
        int slot = s_idxmap[p];
        float4 v = make_float4(0.f, 0.f, 0.f, 0.f);
        if (s_dig[slot] == 0xFFFFu) {
            int r = s_prank[slot];
            v = (r < WHATROWS) ? s_what4[r * 16 + c] : __ldg(&wl4[slot * 16 + c]);
        }
        ow4[i] = v;
    }
}

extern "C" void kernel_launch(void* const* d_in, const int* in_sizes, int n_in,
                              void* d_out, int out_size) {
    const float* z_where      = (const float*)d_in[0];
    const float* z_present    = (const float*)d_in[1];
    const float* z_what_loc   = (const float*)d_in[2];
    // d_in[3] = z_what_scale  (never read)
    const float* z_depth_loc  = (const float*)d_in[4];
    // d_in[5] = z_depth_scale (never read)
    const float* neg_priority = (const float*)d_in[6];

    const int B = in_sizes[6] / NSLOTS;
    const int K = out_size / (B * 70);

    cudaFuncSetAttribute(latent_handler_kernel,
                         cudaFuncAttributeMaxDynamicSharedMemorySize, SMEM_BYTES);

    latent_handler_kernel<<<B, TPB, SMEM_BYTES>>>(z_where, z_present, z_what_loc,
                                                  z_depth_loc, neg_priority,
                                                  (float*)d_out, B, K);
}